// round 1
// baseline (speedup 1.0000x reference)
#include <cuda_runtime.h>

#define LSZ   4096
#define BATCH 64
#define R1    48
#define R2    16
#define NIN   1024
#define FCN   512
#define NCLS  10

// ---------------- scratch (device globals; no allocation allowed) ----------------
__device__ float g_da1[LSZ], g_db1[LSZ], g_da2[LSZ], g_db2[LSZ];
__device__ float g_Gt1[R1*LSZ], g_Ht1[R1*LSZ];
__device__ float g_Gt2[R2*LSZ], g_Ht2[R2*LSZ];
__device__ float g_Mrot[(size_t)LSZ*LSZ];   // 64 MB
__device__ float g_tot[32*LSZ];
__device__ float g_P[32*LSZ];
__device__ float g_z1[BATCH*LSZ];
__device__ float g_z2[BATCH*LSZ];
__device__ float g_h2[BATCH*LSZ];
__device__ float g_Ypart[8*BATCH*LSZ];      // split-K partials, 8 MB

// ---------------- cumprod scan: d[0]=1, d[j]=prod_{k<j} subd[k] ----------------
__global__ void scan_kernel(const float* __restrict__ sA1, const float* __restrict__ sB1,
                            const float* __restrict__ sA2, const float* __restrict__ sB2) {
    const float* src; float* dst;
    if      (blockIdx.x == 0) { src = sA1; dst = g_da1; }
    else if (blockIdx.x == 1) { src = sB1; dst = g_db1; }
    else if (blockIdx.x == 2) { src = sA2; dst = g_da2; }
    else                      { src = sB2; dst = g_db2; }

    __shared__ float part[1024];
    int tid = threadIdx.x;
    float v[4]; float p = 1.f;
#pragma unroll
    for (int j = 0; j < 4; j++) {
        int idx = tid * 4 + j;
        float s = (idx < LSZ - 1) ? src[idx] : 1.f;
        p *= s; v[j] = p;
    }
    part[tid] = p; __syncthreads();
    for (int off = 1; off < 1024; off <<= 1) {
        float x = part[tid];
        float m = (tid >= off) ? part[tid - off] : 1.f;
        __syncthreads();
        part[tid] = x * m;
        __syncthreads();
    }
    float excl = (tid == 0) ? 1.f : part[tid - 1];
    if (tid == 0) dst[0] = 1.f;
#pragma unroll
    for (int j = 0; j < 4; j++) {
        int idx = tid * 4 + j;
        if (idx < LSZ - 1) dst[idx + 1] = excl * v[j];
    }
}

// ---------------- prep: Gt=G/da, Ht=H/db, z1 = db1 * pad(x) ----------------
__global__ void prep_kernel(const float* __restrict__ G1, const float* __restrict__ H1,
                            const float* __restrict__ G2, const float* __restrict__ H2,
                            const float* __restrict__ x) {
    int tid = blockIdx.x * blockDim.x + threadIdx.x;
    int j = tid & (LSZ - 1);
    if (tid < R1 * LSZ) {
        g_Gt1[tid] = G1[tid] / g_da1[j];
        g_Ht1[tid] = H1[tid] / g_db1[j];
    }
    if (tid < R2 * LSZ) {
        g_Gt2[tid] = G2[tid] / g_da2[j];
        g_Ht2[tid] = H2[tid] / g_db2[j];
    }
    if (tid < BATCH * LSZ) {
        int b = tid >> 12;
        g_z1[tid] = (j < NIN) ? x[b * NIN + j] * g_db1[j] : 0.f;
    }
}

// ---------------- Qrot = Gt^T Ht in rotated layout + reset-aware tile totals ----------------
// Qrot[t][c] = sum_i Gt[i][t] * Ht[i][(t+c) mod n]
// tile: 128 t-rows (blockIdx.y) x 128 c-cols (blockIdx.x); 256 thr, 8x8 micro (interleave 16)
template <int R>
__global__ __launch_bounds__(256) void qrot_kernel() {
    const float* __restrict__ Gt = (R == R1) ? g_Gt1 : g_Gt2;
    const float* __restrict__ Ht = (R == R1) ? g_Ht1 : g_Ht2;
    extern __shared__ float sh[];
    float* sA  = sh;               // R*128
    float* sB  = sh + R * 128;     // R*256
    float* red = sB + R * 256;     // 16*128

    int t0 = blockIdx.y << 7, c0 = blockIdx.x << 7;
    int base = t0 + c0;
    for (int idx = threadIdx.x; idx < R * 128; idx += 256) {
        int i = idx >> 7, tt = idx & 127;
        sA[idx] = Gt[i * LSZ + t0 + tt];
    }
    for (int idx = threadIdx.x; idx < R * 256; idx += 256) {
        int i = idx >> 8, s = idx & 255;
        sB[idx] = Ht[i * LSZ + ((base + s) & (LSZ - 1))];
    }
    __syncthreads();

    int tx = threadIdx.x & 15, ty = threadIdx.x >> 4;
    float acc[8][8];
#pragma unroll
    for (int u = 0; u < 8; u++)
#pragma unroll
        for (int v = 0; v < 8; v++) acc[u][v] = 0.f;

    for (int i = 0; i < R; i++) {
        float a[8], b[15];
#pragma unroll
        for (int u = 0; u < 8; u++) a[u] = sA[i * 128 + ty + 16 * u];
#pragma unroll
        for (int s = 0; s < 15; s++) b[s] = sB[i * 256 + tx + ty + 16 * s];
#pragma unroll
        for (int u = 0; u < 8; u++)
#pragma unroll
            for (int v = 0; v < 8; v++) acc[u][v] = fmaf(a[u], b[u + v], acc[u][v]);
    }

    // store Qrot + reset-aware column partials
    float colsum[8];
#pragma unroll
    for (int v = 0; v < 8; v++) colsum[v] = 0.f;
#pragma unroll
    for (int u = 0; u < 8; u++) {
        int t = t0 + ty + 16 * u;
#pragma unroll
        for (int v = 0; v < 8; v++) {
            int c = c0 + tx + 16 * v;
            g_Mrot[(size_t)t * LSZ + c] = acc[u][v];
            int s0 = (c == 0) ? 0 : (LSZ - c);   // diagonal reset row for column c
            bool inc = (s0 <= t0) || (s0 >= t0 + 128) || (t >= s0);
            if (inc) colsum[v] += acc[u][v];
        }
    }
#pragma unroll
    for (int v = 0; v < 8; v++) red[ty * 128 + tx + 16 * v] = colsum[v];
    __syncthreads();
    if (threadIdx.x < 128) {
        float s = 0.f;
#pragma unroll
        for (int y = 0; y < 16; y++) s += red[y * 128 + threadIdx.x];
        g_tot[blockIdx.y * LSZ + c0 + threadIdx.x] = s;
    }
}

// ---------------- exclusive scan of tile totals per column ----------------
__global__ void scanP_kernel() {
    int c = blockIdx.x * blockDim.x + threadIdx.x;
    float run = 0.f;
#pragma unroll
    for (int k = 0; k < 32; k++) {
        g_P[k * LSZ + c] = run;
        run += g_tot[k * LSZ + c];
    }
}

// ---------------- segmented diagonal cumsum (columns of rotated layout) ----------------
__global__ void cumsum_kernel() {
    int c = blockIdx.x * 256 + threadIdx.x;
    int k = blockIdx.y;
    int t0 = k << 7;
    int s0 = (c == 0) ? 0 : (LSZ - c);
    float base = g_P[k * LSZ + c];
    if (s0 <= t0) base -= g_P[(s0 >> 7) * LSZ + c];  // segment B: drop pre-reset tiles
    float acc = base;
    size_t idx0 = (size_t)t0 * LSZ + c;
#pragma unroll 4
    for (int r = 0; r < 128; r++) {
        int t = t0 + r;
        float q = g_Mrot[idx0 + (size_t)r * LSZ];
        if (t == s0) acc = 0.f;
        acc += q;
        g_Mrot[idx0 + (size_t)r * LSZ] = acc;
    }
}

// ---------------- main GEMM: Ypart[k][b][t] = sum_{w in k-slice} M0[t][w] z[b][w] ----------------
// M0[t][w] read from Mrot[t][(w-t) mod n] during the smem load (unrotate-on-load)
__global__ __launch_bounds__(256) void skewgemm_kernel(int layer) {
    const float* __restrict__ z = layer ? g_z2 : g_z1;
    extern __shared__ float sh[];
    float* sM = sh;                 // 128 x 129
    float* sz = sh + 128 * 129;     // 64 x 129
    int t0  = blockIdx.x << 7;
    int w0b = blockIdx.y << 9;
    int tx = threadIdx.x & 15, ty = threadIdx.x >> 4;
    float acc[8][4];
#pragma unroll
    for (int u = 0; u < 8; u++)
#pragma unroll
        for (int v = 0; v < 4; v++) acc[u][v] = 0.f;

    for (int wc = 0; wc < 512; wc += 128) {
        int w0 = w0b + wc;
        for (int idx = threadIdx.x; idx < 128 * 128; idx += 256) {
            int row = idx >> 7, col = idx & 127;
            int t = t0 + row;
            sM[row * 129 + col] = g_Mrot[(size_t)t * LSZ + ((w0 + col - t) & (LSZ - 1))];
        }
        for (int idx = threadIdx.x; idx < 64 * 128; idx += 256) {
            int b = idx >> 7, col = idx & 127;
            sz[b * 129 + col] = z[b * LSZ + w0 + col];
        }
        __syncthreads();
#pragma unroll 4
        for (int ww = 0; ww < 128; ww++) {
            float a[8], zb[4];
#pragma unroll
            for (int u = 0; u < 8; u++) a[u] = sM[(tx + 16 * u) * 129 + ww];
#pragma unroll
            for (int v = 0; v < 4; v++) zb[v] = sz[(ty + 16 * v) * 129 + ww];
#pragma unroll
            for (int u = 0; u < 8; u++)
#pragma unroll
                for (int v = 0; v < 4; v++) acc[u][v] = fmaf(a[u], zb[v], acc[u][v]);
        }
        __syncthreads();
    }
#pragma unroll
    for (int u = 0; u < 8; u++) {
        int t = t0 + tx + 16 * u;
#pragma unroll
        for (int v = 0; v < 4; v++) {
            int b = ty + 16 * v;
            g_Ypart[((size_t)blockIdx.y * BATCH + b) * LSZ + t] = acc[u][v];
        }
    }
}

// ---------------- epilogue: reduce split-K, bias+relu+da; layer0 also folds db2 ----------------
__global__ void epilogue_kernel(const float* __restrict__ bias, int layer) {
    int idx = blockIdx.x * 256 + threadIdx.x;
    if (idx >= BATCH * LSZ) return;
    int t = idx & (LSZ - 1);
    float s = 0.f;
#pragma unroll
    for (int k = 0; k < 8; k++) s += g_Ypart[(size_t)k * BATCH * LSZ + idx];
    float da = layer ? g_da2[t] : g_da1[t];
    float h = fmaxf(da * s + bias[t], 0.f);
    if (layer == 0) g_z2[idx] = h * g_db2[t];
    else            g_h2[idx] = h;
}

// ---------------- logits: out[b][c] = h2[b, :512] . W[c] + bl[c] ----------------
__global__ void logits_kernel(const float* __restrict__ W, const float* __restrict__ bl,
                              float* __restrict__ out) {
    int b = blockIdx.x;
    int cls = threadIdx.x >> 5;
    int lane = threadIdx.x & 31;
    float s = 0.f;
#pragma unroll
    for (int m = 0; m < 16; m++) {
        int j = lane + 32 * m;
        s = fmaf(g_h2[b * LSZ + j], W[cls * FCN + j], s);
    }
#pragma unroll
    for (int off = 16; off; off >>= 1) s += __shfl_down_sync(0xffffffffu, s, off);
    if (lane == 0) out[b * NCLS + cls] = s + bl[cls];
}

// ---------------- launch ----------------
extern "C" void kernel_launch(void* const* d_in, const int* in_sizes, int n_in,
                              void* d_out, int out_size) {
    const float* x    = (const float*)d_in[0];
    const float* G1   = (const float*)d_in[1];
    const float* H1   = (const float*)d_in[2];
    const float* sdA1 = (const float*)d_in[3];
    const float* sdB1 = (const float*)d_in[4];
    const float* b1   = (const float*)d_in[5];
    const float* G2   = (const float*)d_in[6];
    const float* H2   = (const float*)d_in[7];
    const float* sdA2 = (const float*)d_in[8];
    const float* sdB2 = (const float*)d_in[9];
    const float* b2   = (const float*)d_in[10];
    const float* W    = (const float*)d_in[11];
    const float* bl   = (const float*)d_in[12];
    float* out = (float*)d_out;

    const int QSM1 = (R1 * 128 + R1 * 256 + 16 * 128) * 4;  // 81920
    const int QSM2 = (R2 * 128 + R2 * 256 + 16 * 128) * 4;  // 32768
    const int GSM  = (128 * 129 + 64 * 129) * 4;            // 99072

    cudaFuncSetAttribute(qrot_kernel<R1>, cudaFuncAttributeMaxDynamicSharedMemorySize, QSM1);
    cudaFuncSetAttribute(qrot_kernel<R2>, cudaFuncAttributeMaxDynamicSharedMemorySize, QSM2);
    cudaFuncSetAttribute(skewgemm_kernel, cudaFuncAttributeMaxDynamicSharedMemorySize, GSM);

    scan_kernel<<<4, 1024>>>(sdA1, sdB1, sdA2, sdB2);
    prep_kernel<<<1024, 256>>>(G1, H1, G2, H2, x);

    // layer 1
    qrot_kernel<R1><<<dim3(32, 32), 256, QSM1>>>();
    scanP_kernel<<<16, 256>>>();
    cumsum_kernel<<<dim3(16, 32), 256>>>();
    skewgemm_kernel<<<dim3(32, 8), 256, GSM>>>(0);
    epilogue_kernel<<<1024, 256>>>(b1, 0);

    // layer 2
    qrot_kernel<R2><<<dim3(32, 32), 256, QSM2>>>();
    scanP_kernel<<<16, 256>>>();
    cumsum_kernel<<<dim3(16, 32), 256>>>();
    skewgemm_kernel<<<dim3(32, 8), 256, GSM>>>(1);
    epilogue_kernel<<<1024, 256>>>(b2, 1);

    logits_kernel<<<64, 320>>>(W, bl, out);
}